// round 3
// baseline (speedup 1.0000x reference)
#include <cuda_runtime.h>
#include <math.h>

#define D_MODEL 512
#define HEADS   8
#define DKH     64
#define SEQ     2048
#define BATCH   4
#define D_FF    1024
#define NROWS   (BATCH*SEQ)   // 8192

// Scratch (static device arrays — no allocation at runtime)
__device__ float g_x [NROWS * D_MODEL];   // running residual stream
__device__ float g_xn[NROWS * D_MODEL];   // layernorm output
__device__ float g_h [NROWS * D_FF];      // FFN hidden

// ---------------------------------------------------------------------------
// LayerNorm: one block per row (512 elems), 128 threads x float4
// ---------------------------------------------------------------------------
__global__ void ln_kernel(const float* __restrict__ x,
                          const float* __restrict__ gamma,
                          const float* __restrict__ beta,
                          float* __restrict__ y) {
    int row = blockIdx.x;
    int t   = threadIdx.x;
    const float4* xr = (const float4*)(x + (size_t)row * D_MODEL);
    float4 v = xr[t];
    float s  = v.x + v.y + v.z + v.w;
    float ss = v.x*v.x + v.y*v.y + v.z*v.z + v.w*v.w;
    #pragma unroll
    for (int o = 16; o > 0; o >>= 1) {
        s  += __shfl_xor_sync(0xffffffffu, s,  o);
        ss += __shfl_xor_sync(0xffffffffu, ss, o);
    }
    __shared__ float as[4], ass[4];
    int w = t >> 5;
    if ((t & 31) == 0) { as[w] = s; ass[w] = ss; }
    __syncthreads();
    s  = as[0]  + as[1]  + as[2]  + as[3];
    ss = ass[0] + ass[1] + ass[2] + ass[3];
    float mu  = s * (1.0f / D_MODEL);
    float var = ss * (1.0f / D_MODEL) - mu * mu;
    float rs  = rsqrtf(var + 1e-5f);
    float4 g4 = ((const float4*)gamma)[t];
    float4 b4 = ((const float4*)beta)[t];
    float4 o4;
    o4.x = (v.x - mu) * rs * g4.x + b4.x;
    o4.y = (v.y - mu) * rs * g4.y + b4.y;
    o4.z = (v.z - mu) * rs * g4.z + b4.z;
    o4.w = (v.w - mu) * rs * g4.w + b4.w;
    ((float4*)(y + (size_t)row * D_MODEL))[t] = o4;
}

// ---------------------------------------------------------------------------
// Flash attention (fp32 SIMT). grid = (SEQ/64, HEADS, BATCH), block = 256.
// Q tile 64 rows; loop over 32 K-tiles of 64; online softmax.
// out[row, h*64+d] = res[row, h*64+d] + softmax(QK^T/8 (+mask)) @ V
// ---------------------------------------------------------------------------
#define ATTN_SMEM_FLOATS (64*65*3 + 64*64 + 3*64)
#define ATTN_SMEM_BYTES  (ATTN_SMEM_FLOATS * 4)

__global__ void attn_kernel(const float* __restrict__ Q,
                            const float* __restrict__ KV,
                            const int*   __restrict__ mask,   // may be null
                            const float* __restrict__ res,
                            float* __restrict__ out) {
    extern __shared__ float sm[];
    float* Qt   = sm;               // [64 kk][64 m], stride 65
    float* Kt   = Qt + 64 * 65;     // [64 kk][64 n], stride 65
    float* Vs   = Kt + 64 * 65;     // [64 n][64 d], stride 64
    float* Ps   = Vs + 64 * 64;     // [64 q][64 k], stride 65
    float* rowm = Ps + 64 * 65;
    float* rowl = rowm + 64;
    float* corr = rowl + 64;

    const int q0 = blockIdx.x * 64;
    const int h  = blockIdx.y;
    const int b  = blockIdx.z;
    const int tid = threadIdx.x;
    const int tx = tid & 15, ty = tid >> 4;

    // Load Q tile transposed: Qt[kk][m]
    {
        int m  = tid >> 2;
        int kb = (tid & 3) * 16;
        const float* qrow = Q + ((size_t)(b * SEQ + q0 + m)) * D_MODEL + h * DKH + kb;
        #pragma unroll
        for (int c = 0; c < 16; c += 4) {
            float4 v = *(const float4*)(qrow + c);
            Qt[(kb + c + 0) * 65 + m] = v.x;
            Qt[(kb + c + 1) * 65 + m] = v.y;
            Qt[(kb + c + 2) * 65 + m] = v.z;
            Qt[(kb + c + 3) * 65 + m] = v.w;
        }
    }
    if (tid < 64) { rowm[tid] = -INFINITY; rowl[tid] = 0.0f; }

    float o[4][4];
    #pragma unroll
    for (int i = 0; i < 4; i++)
        #pragma unroll
        for (int j = 0; j < 4; j++) o[i][j] = 0.0f;

    for (int kt = 0; kt < SEQ / 64; kt++) {
        const int k0 = kt * 64;
        __syncthreads();   // previous PV done (and Q load on first iter)

        // Load K transposed + V natural
        {
            int n  = tid >> 2;
            int kb = (tid & 3) * 16;
            const float* krow = KV + ((size_t)(b * SEQ + k0 + n)) * D_MODEL + h * DKH + kb;
            #pragma unroll
            for (int c = 0; c < 16; c += 4) {
                float4 v = *(const float4*)(krow + c);
                Kt[(kb + c + 0) * 65 + n] = v.x;
                Kt[(kb + c + 1) * 65 + n] = v.y;
                Kt[(kb + c + 2) * 65 + n] = v.z;
                Kt[(kb + c + 3) * 65 + n] = v.w;
                *(float4*)&Vs[n * 64 + kb + c] = v;   // V == K source tensor
            }
        }
        __syncthreads();

        // S = Q K^T (4x4 per thread)
        float s[4][4];
        #pragma unroll
        for (int i = 0; i < 4; i++)
            #pragma unroll
            for (int j = 0; j < 4; j++) s[i][j] = 0.0f;

        #pragma unroll 8
        for (int kk = 0; kk < 64; kk++) {
            float a[4], bb[4];
            #pragma unroll
            for (int i = 0; i < 4; i++) a[i]  = Qt[kk * 65 + ty * 4 + i];
            #pragma unroll
            for (int j = 0; j < 4; j++) bb[j] = Kt[kk * 65 + tx * 4 + j];
            #pragma unroll
            for (int i = 0; i < 4; i++)
                #pragma unroll
                for (int j = 0; j < 4; j++) s[i][j] += a[i] * bb[j];
        }
        #pragma unroll
        for (int i = 0; i < 4; i++)
            #pragma unroll
            for (int j = 0; j < 4; j++) s[i][j] *= 0.125f;   // 1/sqrt(64)

        if (mask != nullptr) {
            #pragma unroll
            for (int i = 0; i < 4; i++) {
                const int4 m4 = *(const int4*)(mask +
                    ((size_t)b * SEQ + (q0 + ty * 4 + i)) * SEQ + k0 + tx * 4);
                if (m4.x == 0) s[i][0] = -1e9f;
                if (m4.y == 0) s[i][1] = -1e9f;
                if (m4.z == 0) s[i][2] = -1e9f;
                if (m4.w == 0) s[i][3] = -1e9f;
            }
        }
        #pragma unroll
        for (int i = 0; i < 4; i++)
            #pragma unroll
            for (int j = 0; j < 4; j++)
                Ps[(ty * 4 + i) * 65 + tx * 4 + j] = s[i][j];
        __syncthreads();

        // Online softmax bookkeeping (one thread per row)
        if (tid < 64) {
            float* pr = Ps + tid * 65;
            float tm = -INFINITY;
            #pragma unroll 8
            for (int k = 0; k < 64; k++) tm = fmaxf(tm, pr[k]);
            float mold = rowm[tid];
            float mnew = fmaxf(mold, tm);
            float c = __expf(mold - mnew);
            float sum = 0.0f;
            #pragma unroll 8
            for (int k = 0; k < 64; k++) {
                float e = __expf(pr[k] - mnew);
                pr[k] = e;
                sum += e;
            }
            rowm[tid] = mnew;
            rowl[tid] = rowl[tid] * c + sum;
            corr[tid] = c;
        }
        __syncthreads();

        // Rescale accumulators + O += P V
        float cf[4];
        #pragma unroll
        for (int i = 0; i < 4; i++) cf[i] = corr[ty * 4 + i];
        #pragma unroll
        for (int i = 0; i < 4; i++)
            #pragma unroll
            for (int j = 0; j < 4; j++) o[i][j] *= cf[i];

        #pragma unroll 8
        for (int kk = 0; kk < 64; kk++) {
            float p[4];
            #pragma unroll
            for (int i = 0; i < 4; i++) p[i] = Ps[(ty * 4 + i) * 65 + kk];
            float4 v4 = *(const float4*)&Vs[kk * 64 + tx * 4];
            #pragma unroll
            for (int i = 0; i < 4; i++) {
                o[i][0] += p[i] * v4.x;
                o[i][1] += p[i] * v4.y;
                o[i][2] += p[i] * v4.z;
                o[i][3] += p[i] * v4.w;
            }
        }
    }

    // Epilogue: normalize + residual add
    float inv[4];
    #pragma unroll
    for (int i = 0; i < 4; i++) inv[i] = 1.0f / rowl[ty * 4 + i];
    #pragma unroll
    for (int i = 0; i < 4; i++) {
        size_t idx = ((size_t)(b * SEQ + q0 + ty * 4 + i)) * D_MODEL + h * DKH + tx * 4;
        float4 r4 = *(const float4*)(res + idx);
        float4 o4;
        o4.x = r4.x + o[i][0] * inv[i];
        o4.y = r4.y + o[i][1] * inv[i];
        o4.z = r4.z + o[i][2] * inv[i];
        o4.w = r4.w + o[i][3] * inv[i];
        *(float4*)(out + idx) = o4;
    }
}

// ---------------------------------------------------------------------------
// Tiled GEMM: C[M,N] = A[M,K] @ B[K,N] + bias (+ReLU) (+res). 64x64x16 tiles.
// grid = (N/64, M/64), block = 256, 4x4 per thread.
// ---------------------------------------------------------------------------
template<bool RELU, bool RES>
__global__ void gemm_kernel(const float* __restrict__ A,
                            const float* __restrict__ B,
                            const float* __restrict__ bias,
                            const float* __restrict__ res,
                            float* __restrict__ C,
                            int M, int N, int K) {
    __shared__ float As[16 * 65];   // As[k][m], stride 65
    __shared__ float Bs[16 * 64];   // Bs[k][n]

    const int n0 = blockIdx.x * 64;
    const int m0 = blockIdx.y * 64;
    const int tid = threadIdx.x;
    const int tx = tid & 15, ty = tid >> 4;

    float acc[4][4];
    #pragma unroll
    for (int i = 0; i < 4; i++)
        #pragma unroll
        for (int j = 0; j < 4; j++) acc[i][j] = 0.0f;

    for (int k0 = 0; k0 < K; k0 += 16) {
        {
            int m  = tid >> 2;
            int kb = (tid & 3) * 4;
            float4 av = *(const float4*)(A + (size_t)(m0 + m) * K + k0 + kb);
            As[(kb + 0) * 65 + m] = av.x;
            As[(kb + 1) * 65 + m] = av.y;
            As[(kb + 2) * 65 + m] = av.z;
            As[(kb + 3) * 65 + m] = av.w;
            int kk = tid >> 4;
            int n  = (tid & 15) * 4;
            float4 bv = *(const float4*)(B + (size_t)(k0 + kk) * N + n0 + n);
            *(float4*)&Bs[kk * 64 + n] = bv;
        }
        __syncthreads();
        #pragma unroll
        for (int kk = 0; kk < 16; kk++) {
            float a[4];
            #pragma unroll
            for (int i = 0; i < 4; i++) a[i] = As[kk * 65 + ty * 4 + i];
            float4 bv = *(const float4*)&Bs[kk * 64 + tx * 4];
            #pragma unroll
            for (int i = 0; i < 4; i++) {
                acc[i][0] += a[i] * bv.x;
                acc[i][1] += a[i] * bv.y;
                acc[i][2] += a[i] * bv.z;
                acc[i][3] += a[i] * bv.w;
            }
        }
        __syncthreads();
    }

    #pragma unroll
    for (int i = 0; i < 4; i++) {
        size_t idx = (size_t)(m0 + ty * 4 + i) * N + n0 + tx * 4;
        float4 bi = *(const float4*)(bias + n0 + tx * 4);
        float4 v;
        v.x = acc[i][0] + bi.x;
        v.y = acc[i][1] + bi.y;
        v.z = acc[i][2] + bi.z;
        v.w = acc[i][3] + bi.w;
        if (RELU) {
            v.x = fmaxf(v.x, 0.0f); v.y = fmaxf(v.y, 0.0f);
            v.z = fmaxf(v.z, 0.0f); v.w = fmaxf(v.w, 0.0f);
        }
        if (RES) {
            float4 r4 = *(const float4*)(res + idx);
            v.x += r4.x; v.y += r4.y; v.z += r4.z; v.w += r4.w;
        }
        *(float4*)(C + idx) = v;
    }
}

// ---------------------------------------------------------------------------
extern "C" void kernel_launch(void* const* d_in, const int* in_sizes, int n_in,
                              void* d_out, int out_size) {
    const float* x    = (const float*)d_in[0];
    const float* enc  = (const float*)d_in[1];
    const int*   mask = (const int*)  d_in[2];
    const float* ln1g = (const float*)d_in[3];
    const float* ln1b = (const float*)d_in[4];
    const float* ln2g = (const float*)d_in[5];
    const float* ln2b = (const float*)d_in[6];
    const float* ln3g = (const float*)d_in[7];
    const float* ln3b = (const float*)d_in[8];
    const float* W1   = (const float*)d_in[9];
    const float* b1   = (const float*)d_in[10];
    const float* W2   = (const float*)d_in[11];
    const float* b2   = (const float*)d_in[12];
    float* out = (float*)d_out;

    float *gx, *gxn, *gh;
    cudaGetSymbolAddress((void**)&gx,  g_x);
    cudaGetSymbolAddress((void**)&gxn, g_xn);
    cudaGetSymbolAddress((void**)&gh,  g_h);

    cudaFuncSetAttribute(attn_kernel,
                         cudaFuncAttributeMaxDynamicSharedMemorySize,
                         ATTN_SMEM_BYTES);

    dim3 attn_grid(SEQ / 64, HEADS, BATCH);

    // 1) x1 = LN1(x); x' = x + selfattn(x1, mask)
    ln_kernel<<<NROWS, 128>>>(x, ln1g, ln1b, gxn);
    attn_kernel<<<attn_grid, 256, ATTN_SMEM_BYTES>>>(gxn, gxn, mask, x, gx);

    // 2) x1 = LN2(x'); x'' = x' + crossattn(x1, enc)
    ln_kernel<<<NROWS, 128>>>(gx, ln2g, ln2b, gxn);
    attn_kernel<<<attn_grid, 256, ATTN_SMEM_BYTES>>>(gxn, enc, nullptr, gx, gx);

    // 3) x1 = LN3(x''); out = x'' + relu(x1 W1 + b1) W2 + b2
    ln_kernel<<<NROWS, 128>>>(gx, ln3g, ln3b, gxn);
    gemm_kernel<true,  false><<<dim3(D_FF / 64,    NROWS / 64), 256>>>(
        gxn, W1, b1, nullptr, gh, NROWS, D_FF, D_MODEL);
    gemm_kernel<false, true ><<<dim3(D_MODEL / 64, NROWS / 64), 256>>>(
        gh, W2, b2, gx, out, NROWS, D_MODEL, D_FF);
}

// round 4
// speedup vs baseline: 1.0014x; 1.0014x over previous
#include <cuda_runtime.h>
#include <math.h>

#define D_MODEL 512
#define HEADS   8
#define DKH     64
#define SEQ     2048
#define BATCH   4
#define D_FF    1024
#define NROWS   (BATCH*SEQ)   // 8192

// Scratch (static device arrays — no allocation at runtime)
__device__ float g_x [NROWS * D_MODEL];   // running residual stream
__device__ float g_xn[NROWS * D_MODEL];   // layernorm output
__device__ float g_h [NROWS * D_FF];      // FFN hidden

// ---------------------------------------------------------------------------
// LayerNorm: one block per row (512 elems), 128 threads x float4
// ---------------------------------------------------------------------------
__global__ void ln_kernel(const float* __restrict__ x,
                          const float* __restrict__ gamma,
                          const float* __restrict__ beta,
                          float* __restrict__ y) {
    int row = blockIdx.x;
    int t   = threadIdx.x;
    const float4* xr = (const float4*)(x + (size_t)row * D_MODEL);
    float4 v = xr[t];
    float s  = v.x + v.y + v.z + v.w;
    float ss = v.x*v.x + v.y*v.y + v.z*v.z + v.w*v.w;
    #pragma unroll
    for (int o = 16; o > 0; o >>= 1) {
        s  += __shfl_xor_sync(0xffffffffu, s,  o);
        ss += __shfl_xor_sync(0xffffffffu, ss, o);
    }
    __shared__ float as[4], ass[4];
    int w = t >> 5;
    if ((t & 31) == 0) { as[w] = s; ass[w] = ss; }
    __syncthreads();
    s  = as[0]  + as[1]  + as[2]  + as[3];
    ss = ass[0] + ass[1] + ass[2] + ass[3];
    float mu  = s * (1.0f / D_MODEL);
    float var = ss * (1.0f / D_MODEL) - mu * mu;
    float rs  = rsqrtf(var + 1e-5f);
    float4 g4 = ((const float4*)gamma)[t];
    float4 b4 = ((const float4*)beta)[t];
    float4 o4;
    o4.x = (v.x - mu) * rs * g4.x + b4.x;
    o4.y = (v.y - mu) * rs * g4.y + b4.y;
    o4.z = (v.z - mu) * rs * g4.z + b4.z;
    o4.w = (v.w - mu) * rs * g4.w + b4.w;
    ((float4*)(y + (size_t)row * D_MODEL))[t] = o4;
}

// ---------------------------------------------------------------------------
// Flash attention (fp32 SIMT). grid = (SEQ/64, HEADS, BATCH), block = 256.
// Q tile 64 rows; loop over 32 K-tiles of 64; online softmax.
// out[row, h*64+d] = res[row, h*64+d] + softmax(QK^T/8 (+mask)) @ V
// ---------------------------------------------------------------------------
#define ATTN_SMEM_FLOATS (64*65*3 + 64*64 + 3*64)
#define ATTN_SMEM_BYTES  (ATTN_SMEM_FLOATS * 4)

__global__ void attn_kernel(const float* __restrict__ Q,
                            const float* __restrict__ KV,
                            const int*   __restrict__ mask,   // may be null
                            const float* __restrict__ res,
                            float* __restrict__ out) {
    extern __shared__ float sm[];
    float* Qt   = sm;               // [64 kk][64 m], stride 65
    float* Kt   = Qt + 64 * 65;     // [64 kk][64 n], stride 65
    float* Vs   = Kt + 64 * 65;     // [64 n][64 d], stride 64
    float* Ps   = Vs + 64 * 64;     // [64 q][64 k], stride 65
    float* rowm = Ps + 64 * 65;
    float* rowl = rowm + 64;
    float* corr = rowl + 64;

    const int q0 = blockIdx.x * 64;
    const int h  = blockIdx.y;
    const int b  = blockIdx.z;
    const int tid = threadIdx.x;
    const int tx = tid & 15, ty = tid >> 4;

    // Load Q tile transposed: Qt[kk][m]
    {
        int m  = tid >> 2;
        int kb = (tid & 3) * 16;
        const float* qrow = Q + ((size_t)(b * SEQ + q0 + m)) * D_MODEL + h * DKH + kb;
        #pragma unroll
        for (int c = 0; c < 16; c += 4) {
            float4 v = *(const float4*)(qrow + c);
            Qt[(kb + c + 0) * 65 + m] = v.x;
            Qt[(kb + c + 1) * 65 + m] = v.y;
            Qt[(kb + c + 2) * 65 + m] = v.z;
            Qt[(kb + c + 3) * 65 + m] = v.w;
        }
    }
    if (tid < 64) { rowm[tid] = -INFINITY; rowl[tid] = 0.0f; }

    float o[4][4];
    #pragma unroll
    for (int i = 0; i < 4; i++)
        #pragma unroll
        for (int j = 0; j < 4; j++) o[i][j] = 0.0f;

    for (int kt = 0; kt < SEQ / 64; kt++) {
        const int k0 = kt * 64;
        __syncthreads();   // previous PV done (and Q load on first iter)

        // Load K transposed + V natural
        {
            int n  = tid >> 2;
            int kb = (tid & 3) * 16;
            const float* krow = KV + ((size_t)(b * SEQ + k0 + n)) * D_MODEL + h * DKH + kb;
            #pragma unroll
            for (int c = 0; c < 16; c += 4) {
                float4 v = *(const float4*)(krow + c);
                Kt[(kb + c + 0) * 65 + n] = v.x;
                Kt[(kb + c + 1) * 65 + n] = v.y;
                Kt[(kb + c + 2) * 65 + n] = v.z;
                Kt[(kb + c + 3) * 65 + n] = v.w;
                *(float4*)&Vs[n * 64 + kb + c] = v;   // V == K source tensor
            }
        }
        __syncthreads();

        // S = Q K^T (4x4 per thread)
        float s[4][4];
        #pragma unroll
        for (int i = 0; i < 4; i++)
            #pragma unroll
            for (int j = 0; j < 4; j++) s[i][j] = 0.0f;

        #pragma unroll 8
        for (int kk = 0; kk < 64; kk++) {
            float a[4], bb[4];
            #pragma unroll
            for (int i = 0; i < 4; i++) a[i]  = Qt[kk * 65 + ty * 4 + i];
            #pragma unroll
            for (int j = 0; j < 4; j++) bb[j] = Kt[kk * 65 + tx * 4 + j];
            #pragma unroll
            for (int i = 0; i < 4; i++)
                #pragma unroll
                for (int j = 0; j < 4; j++) s[i][j] += a[i] * bb[j];
        }
        #pragma unroll
        for (int i = 0; i < 4; i++)
            #pragma unroll
            for (int j = 0; j < 4; j++) s[i][j] *= 0.125f;   // 1/sqrt(64)

        if (mask != nullptr) {
            #pragma unroll
            for (int i = 0; i < 4; i++) {
                const int4 m4 = *(const int4*)(mask +
                    ((size_t)b * SEQ + (q0 + ty * 4 + i)) * SEQ + k0 + tx * 4);
                if (m4.x == 0) s[i][0] = -1e9f;
                if (m4.y == 0) s[i][1] = -1e9f;
                if (m4.z == 0) s[i][2] = -1e9f;
                if (m4.w == 0) s[i][3] = -1e9f;
            }
        }
        #pragma unroll
        for (int i = 0; i < 4; i++)
            #pragma unroll
            for (int j = 0; j < 4; j++)
                Ps[(ty * 4 + i) * 65 + tx * 4 + j] = s[i][j];
        __syncthreads();

        // Online softmax bookkeeping (one thread per row)
        if (tid < 64) {
            float* pr = Ps + tid * 65;
            float tm = -INFINITY;
            #pragma unroll 8
            for (int k = 0; k < 64; k++) tm = fmaxf(tm, pr[k]);
            float mold = rowm[tid];
            float mnew = fmaxf(mold, tm);
            float c = __expf(mold - mnew);
            float sum = 0.0f;
            #pragma unroll 8
            for (int k = 0; k < 64; k++) {
                float e = __expf(pr[k] - mnew);
                pr[k] = e;
                sum += e;
            }
            rowm[tid] = mnew;
            rowl[tid] = rowl[tid] * c + sum;
            corr[tid] = c;
        }
        __syncthreads();

        // Rescale accumulators + O += P V
        float cf[4];
        #pragma unroll
        for (int i = 0; i < 4; i++) cf[i] = corr[ty * 4 + i];
        #pragma unroll
        for (int i = 0; i < 4; i++)
            #pragma unroll
            for (int j = 0; j < 4; j++) o[i][j] *= cf[i];

        #pragma unroll 8
        for (int kk = 0; kk < 64; kk++) {
            float p[4];
            #pragma unroll
            for (int i = 0; i < 4; i++) p[i] = Ps[(ty * 4 + i) * 65 + kk];
            float4 v4 = *(const float4*)&Vs[kk * 64 + tx * 4];
            #pragma unroll
            for (int i = 0; i < 4; i++) {
                o[i][0] += p[i] * v4.x;
                o[i][1] += p[i] * v4.y;
                o[i][2] += p[i] * v4.z;
                o[i][3] += p[i] * v4.w;
            }
        }
    }

    // Epilogue: normalize + residual add
    float inv[4];
    #pragma unroll
    for (int i = 0; i < 4; i++) inv[i] = 1.0f / rowl[ty * 4 + i];
    #pragma unroll
    for (int i = 0; i < 4; i++) {
        size_t idx = ((size_t)(b * SEQ + q0 + ty * 4 + i)) * D_MODEL + h * DKH + tx * 4;
        float4 r4 = *(const float4*)(res + idx);
        float4 o4;
        o4.x = r4.x + o[i][0] * inv[i];
        o4.y = r4.y + o[i][1] * inv[i];
        o4.z = r4.z + o[i][2] * inv[i];
        o4.w = r4.w + o[i][3] * inv[i];
        *(float4*)(out + idx) = o4;
    }
}

// ---------------------------------------------------------------------------
// Tiled GEMM: C[M,N] = A[M,K] @ B[K,N] + bias (+ReLU) (+res). 64x64x16 tiles.
// grid = (N/64, M/64), block = 256, 4x4 per thread.
// ---------------------------------------------------------------------------
template<bool RELU, bool RES>
__global__ void gemm_kernel(const float* __restrict__ A,
                            const float* __restrict__ B,
                            const float* __restrict__ bias,
                            const float* __restrict__ res,
                            float* __restrict__ C,
                            int M, int N, int K) {
    __shared__ float As[16 * 65];   // As[k][m], stride 65
    __shared__ float Bs[16 * 64];   // Bs[k][n]

    const int n0 = blockIdx.x * 64;
    const int m0 = blockIdx.y * 64;
    const int tid = threadIdx.x;
    const int tx = tid & 15, ty = tid >> 4;

    float acc[4][4];
    #pragma unroll
    for (int i = 0; i < 4; i++)
        #pragma unroll
        for (int j = 0; j < 4; j++) acc[i][j] = 0.0f;

    for (int k0 = 0; k0 < K; k0 += 16) {
        {
            int m  = tid >> 2;
            int kb = (tid & 3) * 4;
            float4 av = *(const float4*)(A + (size_t)(m0 + m) * K + k0 + kb);
            As[(kb + 0) * 65 + m] = av.x;
            As[(kb + 1) * 65 + m] = av.y;
            As[(kb + 2) * 65 + m] = av.z;
            As[(kb + 3) * 65 + m] = av.w;
            int kk = tid >> 4;
            int n  = (tid & 15) * 4;
            float4 bv = *(const float4*)(B + (size_t)(k0 + kk) * N + n0 + n);
            *(float4*)&Bs[kk * 64 + n] = bv;
        }
        __syncthreads();
        #pragma unroll
        for (int kk = 0; kk < 16; kk++) {
            float a[4];
            #pragma unroll
            for (int i = 0; i < 4; i++) a[i] = As[kk * 65 + ty * 4 + i];
            float4 bv = *(const float4*)&Bs[kk * 64 + tx * 4];
            #pragma unroll
            for (int i = 0; i < 4; i++) {
                acc[i][0] += a[i] * bv.x;
                acc[i][1] += a[i] * bv.y;
                acc[i][2] += a[i] * bv.z;
                acc[i][3] += a[i] * bv.w;
            }
        }
        __syncthreads();
    }

    #pragma unroll
    for (int i = 0; i < 4; i++) {
        size_t idx = (size_t)(m0 + ty * 4 + i) * N + n0 + tx * 4;
        float4 bi = *(const float4*)(bias + n0 + tx * 4);
        float4 v;
        v.x = acc[i][0] + bi.x;
        v.y = acc[i][1] + bi.y;
        v.z = acc[i][2] + bi.z;
        v.w = acc[i][3] + bi.w;
        if (RELU) {
            v.x = fmaxf(v.x, 0.0f); v.y = fmaxf(v.y, 0.0f);
            v.z = fmaxf(v.z, 0.0f); v.w = fmaxf(v.w, 0.0f);
        }
        if (RES) {
            float4 r4 = *(const float4*)(res + idx);
            v.x += r4.x; v.y += r4.y; v.z += r4.z; v.w += r4.w;
        }
        *(float4*)(C + idx) = v;
    }
}

// ---------------------------------------------------------------------------
extern "C" void kernel_launch(void* const* d_in, const int* in_sizes, int n_in,
                              void* d_out, int out_size) {
    const float* x    = (const float*)d_in[0];
    const float* enc  = (const float*)d_in[1];
    const int*   mask = (const int*)  d_in[2];
    const float* ln1g = (const float*)d_in[3];
    const float* ln1b = (const float*)d_in[4];
    const float* ln2g = (const float*)d_in[5];
    const float* ln2b = (const float*)d_in[6];
    const float* ln3g = (const float*)d_in[7];
    const float* ln3b = (const float*)d_in[8];
    const float* W1   = (const float*)d_in[9];
    const float* b1   = (const float*)d_in[10];
    const float* W2   = (const float*)d_in[11];
    const float* b2   = (const float*)d_in[12];
    float* out = (float*)d_out;

    float *gx, *gxn, *gh;
    cudaGetSymbolAddress((void**)&gx,  g_x);
    cudaGetSymbolAddress((void**)&gxn, g_xn);
    cudaGetSymbolAddress((void**)&gh,  g_h);

    cudaFuncSetAttribute(attn_kernel,
                         cudaFuncAttributeMaxDynamicSharedMemorySize,
                         ATTN_SMEM_BYTES);

    dim3 attn_grid(SEQ / 64, HEADS, BATCH);

    // 1) x1 = LN1(x); x' = x + selfattn(x1, mask)
    ln_kernel<<<NROWS, 128>>>(x, ln1g, ln1b, gxn);
    attn_kernel<<<attn_grid, 256, ATTN_SMEM_BYTES>>>(gxn, gxn, mask, x, gx);

    // 2) x1 = LN2(x'); x'' = x' + crossattn(x1, enc)
    ln_kernel<<<NROWS, 128>>>(gx, ln2g, ln2b, gxn);
    attn_kernel<<<attn_grid, 256, ATTN_SMEM_BYTES>>>(gxn, enc, nullptr, gx, gx);

    // 3) x1 = LN3(x''); out = x'' + relu(x1 W1 + b1) W2 + b2
    ln_kernel<<<NROWS, 128>>>(gx, ln3g, ln3b, gxn);
    gemm_kernel<true,  false><<<dim3(D_FF / 64,    NROWS / 64), 256>>>(
        gxn, W1, b1, nullptr, gh, NROWS, D_FF, D_MODEL);
    gemm_kernel<false, true ><<<dim3(D_MODEL / 64, NROWS / 64), 256>>>(
        gh, W2, b2, gx, out, NROWS, D_MODEL, D_FF);
}

// round 5
// speedup vs baseline: 2.7966x; 2.7926x over previous
#include <cuda_runtime.h>
#include <math.h>
#include <stdint.h>

#define D_MODEL 512
#define HEADS   8
#define DKH     64
#define SEQ     2048
#define BATCH   4
#define D_FF    1024
#define NROWS   (BATCH*SEQ)   // 8192

// Scratch (static device arrays — no allocation at runtime)
__device__ float g_x [NROWS * D_MODEL];   // running residual stream
__device__ float g_xn[NROWS * D_MODEL];   // layernorm output
__device__ float g_h [NROWS * D_FF];      // FFN hidden

// ---------------------------------------------------------------------------
// tf32 helpers
// ---------------------------------------------------------------------------
__device__ __forceinline__ uint32_t f2tf(float x) {
    uint32_t r;
    asm("cvt.rna.tf32.f32 %0, %1;" : "=r"(r) : "f"(x));
    return r;
}

// D += A(16x8) * B(8x8); A row-major, B col-major (B[k][n], k contiguous idx)
__device__ __forceinline__ void mma_tf32(float c[4],
                                         uint32_t a0, uint32_t a1, uint32_t a2, uint32_t a3,
                                         uint32_t b0, uint32_t b1) {
    asm volatile(
        "mma.sync.aligned.m16n8k8.row.col.f32.tf32.tf32.f32 "
        "{%0,%1,%2,%3}, {%4,%5,%6,%7}, {%8,%9}, {%0,%1,%2,%3};\n"
        : "+f"(c[0]), "+f"(c[1]), "+f"(c[2]), "+f"(c[3])
        : "r"(a0), "r"(a1), "r"(a2), "r"(a3), "r"(b0), "r"(b1));
}

// ---------------------------------------------------------------------------
// LayerNorm: one block per row (512 elems), 128 threads x float4
// ---------------------------------------------------------------------------
__global__ void ln_kernel(const float* __restrict__ x,
                          const float* __restrict__ gamma,
                          const float* __restrict__ beta,
                          float* __restrict__ y) {
    int row = blockIdx.x;
    int t   = threadIdx.x;
    const float4* xr = (const float4*)(x + (size_t)row * D_MODEL);
    float4 v = xr[t];
    float s  = v.x + v.y + v.z + v.w;
    float ss = v.x*v.x + v.y*v.y + v.z*v.z + v.w*v.w;
    #pragma unroll
    for (int o = 16; o > 0; o >>= 1) {
        s  += __shfl_xor_sync(0xffffffffu, s,  o);
        ss += __shfl_xor_sync(0xffffffffu, ss, o);
    }
    __shared__ float as[4], ass[4];
    int w = t >> 5;
    if ((t & 31) == 0) { as[w] = s; ass[w] = ss; }
    __syncthreads();
    s  = as[0]  + as[1]  + as[2]  + as[3];
    ss = ass[0] + ass[1] + ass[2] + ass[3];
    float mu  = s * (1.0f / D_MODEL);
    float var = ss * (1.0f / D_MODEL) - mu * mu;
    float rs  = rsqrtf(var + 1e-5f);
    float4 g4 = ((const float4*)gamma)[t];
    float4 b4 = ((const float4*)beta)[t];
    float4 o4;
    o4.x = (v.x - mu) * rs * g4.x + b4.x;
    o4.y = (v.y - mu) * rs * g4.y + b4.y;
    o4.z = (v.z - mu) * rs * g4.z + b4.z;
    o4.w = (v.w - mu) * rs * g4.w + b4.w;
    ((float4*)(y + (size_t)row * D_MODEL))[t] = o4;
}

// ---------------------------------------------------------------------------
// Flash attention with mma.sync tf32.
// grid = (SEQ/64, HEADS, BATCH), block = 128 (4 warps).
// Warp w owns Q rows [16w, 16w+16). BN = 64 keys per tile, dk = 64.
// Bank-conflict-free strides: Q/K/P stride 68 (4*g+tig), V stride 72 (8*k+g).
// ---------------------------------------------------------------------------
#define QS_STRIDE 68
#define KS_STRIDE 68
#define VS_STRIDE 72
#define PS_STRIDE 68
#define ATTN_SMEM_U32 (64*QS_STRIDE + 64*KS_STRIDE + 64*VS_STRIDE + 64*PS_STRIDE)
#define ATTN_SMEM_BYTES (ATTN_SMEM_U32 * 4)

__global__ void attn_mma_kernel(const float* __restrict__ Q,
                                const float* __restrict__ KV,
                                const int*   __restrict__ mask,   // may be null
                                const float* __restrict__ res,
                                float* __restrict__ out) {
    extern __shared__ uint32_t sm[];
    uint32_t* Qs = sm;
    uint32_t* Ks = Qs + 64 * QS_STRIDE;
    uint32_t* Vs = Ks + 64 * KS_STRIDE;
    uint32_t* Ps = Vs + 64 * VS_STRIDE;

    const int q0   = blockIdx.x * 64;
    const int h    = blockIdx.y;
    const int b    = blockIdx.z;
    const int tid  = threadIdx.x;
    const int lane = tid & 31;
    const int warp = tid >> 5;
    const int g    = lane >> 2;   // groupID (row within frag)
    const int tig  = lane & 3;    // thread in group

    // Load Q tile [64 x 64] (rows q0.., cols h*64..), tf32-convert
    for (int i = tid; i < 64 * 16; i += 128) {
        int r = i >> 4, cs = (i & 15) << 2;
        float4 v = *(const float4*)(Q + ((size_t)(b * SEQ + q0 + r)) * D_MODEL + h * DKH + cs);
        uint32_t* d = Qs + r * QS_STRIDE + cs;
        d[0] = f2tf(v.x); d[1] = f2tf(v.y); d[2] = f2tf(v.z); d[3] = f2tf(v.w);
    }

    float oacc[8][4];
    #pragma unroll
    for (int i = 0; i < 8; i++)
        #pragma unroll
        for (int j = 0; j < 4; j++) oacc[i][j] = 0.0f;

    float m0 = -INFINITY, m1 = -INFINITY, l0 = 0.0f, l1 = 0.0f;

    for (int kt = 0; kt < SEQ / 64; kt++) {
        const int k0 = kt * 64;
        __syncthreads();   // protect Ks/Vs (prev PV done) and Qs on first iter

        // Load K/V tile (same tensor) [64 x 64], tf32-convert into both buffers
        for (int i = tid; i < 64 * 16; i += 128) {
            int r = i >> 4, cs = (i & 15) << 2;
            float4 v = *(const float4*)(KV + ((size_t)(b * SEQ + k0 + r)) * D_MODEL + h * DKH + cs);
            uint32_t x0 = f2tf(v.x), x1 = f2tf(v.y), x2 = f2tf(v.z), x3 = f2tf(v.w);
            uint32_t* dk = Ks + r * KS_STRIDE + cs;
            dk[0] = x0; dk[1] = x1; dk[2] = x2; dk[3] = x3;
            uint32_t* dv = Vs + r * VS_STRIDE + cs;
            dv[0] = x0; dv[1] = x1; dv[2] = x2; dv[3] = x3;
        }
        __syncthreads();

        // ---- S = Q K^T  (warp: 16 x 64, 8 n-frags) ----
        float sacc[8][4];
        #pragma unroll
        for (int i = 0; i < 8; i++)
            #pragma unroll
            for (int j = 0; j < 4; j++) sacc[i][j] = 0.0f;

        #pragma unroll
        for (int ks = 0; ks < 8; ks++) {
            const int kc = ks * 8;
            const uint32_t* qa = Qs + (warp * 16 + g) * QS_STRIDE + kc + tig;
            uint32_t a0 = qa[0];
            uint32_t a1 = qa[8 * QS_STRIDE];
            uint32_t a2 = qa[4];
            uint32_t a3 = qa[8 * QS_STRIDE + 4];
            #pragma unroll
            for (int nf = 0; nf < 8; nf++) {
                const uint32_t* kb = Ks + (nf * 8 + g) * KS_STRIDE + kc + tig;
                mma_tf32(sacc[nf], a0, a1, a2, a3, kb[0], kb[4]);
            }
        }
        #pragma unroll
        for (int i = 0; i < 8; i++)
            #pragma unroll
            for (int j = 0; j < 4; j++) sacc[i][j] *= 0.125f;

        if (mask != nullptr) {
            const int qr0 = q0 + warp * 16 + g;
            #pragma unroll
            for (int nf = 0; nf < 8; nf++) {
                int kc = k0 + nf * 8 + 2 * tig;
                int2 mA = *(const int2*)(mask + ((size_t)b * SEQ + qr0)     * SEQ + kc);
                int2 mB = *(const int2*)(mask + ((size_t)b * SEQ + qr0 + 8) * SEQ + kc);
                if (mA.x == 0) sacc[nf][0] = -1e9f;
                if (mA.y == 0) sacc[nf][1] = -1e9f;
                if (mB.x == 0) sacc[nf][2] = -1e9f;
                if (mB.y == 0) sacc[nf][3] = -1e9f;
            }
        }

        // ---- online softmax in registers (rows g and g+8, reduce over quad) ----
        float tm0 = -INFINITY, tm1 = -INFINITY;
        #pragma unroll
        for (int nf = 0; nf < 8; nf++) {
            tm0 = fmaxf(tm0, fmaxf(sacc[nf][0], sacc[nf][1]));
            tm1 = fmaxf(tm1, fmaxf(sacc[nf][2], sacc[nf][3]));
        }
        tm0 = fmaxf(tm0, __shfl_xor_sync(0xffffffffu, tm0, 1));
        tm0 = fmaxf(tm0, __shfl_xor_sync(0xffffffffu, tm0, 2));
        tm1 = fmaxf(tm1, __shfl_xor_sync(0xffffffffu, tm1, 1));
        tm1 = fmaxf(tm1, __shfl_xor_sync(0xffffffffu, tm1, 2));

        float mn0 = fmaxf(m0, tm0), mn1 = fmaxf(m1, tm1);
        float c0 = __expf(m0 - mn0), c1 = __expf(m1 - mn1);
        float s0 = 0.0f, s1 = 0.0f;
        #pragma unroll
        for (int nf = 0; nf < 8; nf++) {
            float p0 = __expf(sacc[nf][0] - mn0);
            float p1 = __expf(sacc[nf][1] - mn0);
            float p2 = __expf(sacc[nf][2] - mn1);
            float p3 = __expf(sacc[nf][3] - mn1);
            s0 += p0 + p1; s1 += p2 + p3;
            sacc[nf][0] = p0; sacc[nf][1] = p1; sacc[nf][2] = p2; sacc[nf][3] = p3;
        }
        s0 += __shfl_xor_sync(0xffffffffu, s0, 1);
        s0 += __shfl_xor_sync(0xffffffffu, s0, 2);
        s1 += __shfl_xor_sync(0xffffffffu, s1, 1);
        s1 += __shfl_xor_sync(0xffffffffu, s1, 2);

        m0 = mn0; m1 = mn1;
        l0 = l0 * c0 + s0;
        l1 = l1 * c1 + s1;

        #pragma unroll
        for (int df = 0; df < 8; df++) {
            oacc[df][0] *= c0; oacc[df][1] *= c0;
            oacc[df][2] *= c1; oacc[df][3] *= c1;
        }

        // ---- write P (tf32) to smem, warp-private rows ----
        {
            const int r0 = warp * 16 + g;
            #pragma unroll
            for (int nf = 0; nf < 8; nf++) {
                int col = nf * 8 + 2 * tig;
                uint2 w0, w1;
                w0.x = f2tf(sacc[nf][0]); w0.y = f2tf(sacc[nf][1]);
                w1.x = f2tf(sacc[nf][2]); w1.y = f2tf(sacc[nf][3]);
                *(uint2*)(Ps + r0 * PS_STRIDE + col)       = w0;
                *(uint2*)(Ps + (r0 + 8) * PS_STRIDE + col) = w1;
            }
        }
        __syncwarp();   // P rows are warp-private; warp-level fence suffices

        // ---- O += P V  (A = P 16x64, B = V 64x64) ----
        #pragma unroll
        for (int ks = 0; ks < 8; ks++) {
            const int kc = ks * 8;
            const uint32_t* pa = Ps + (warp * 16 + g) * PS_STRIDE + kc + tig;
            uint32_t a0 = pa[0];
            uint32_t a1 = pa[8 * PS_STRIDE];
            uint32_t a2 = pa[4];
            uint32_t a3 = pa[8 * PS_STRIDE + 4];
            #pragma unroll
            for (int df = 0; df < 8; df++) {
                const uint32_t* vb = Vs + (kc + tig) * VS_STRIDE + df * 8 + g;
                mma_tf32(oacc[df], a0, a1, a2, a3, vb[0], vb[4 * VS_STRIDE]);
            }
        }
    }

    // ---- epilogue: normalize + residual ----
    float inv0 = 1.0f / l0, inv1 = 1.0f / l1;
    const int r0 = q0 + warp * 16 + g;
    #pragma unroll
    for (int df = 0; df < 8; df++) {
        size_t idx0 = ((size_t)(b * SEQ + r0)) * D_MODEL + h * DKH + df * 8 + 2 * tig;
        size_t idx1 = idx0 + (size_t)8 * D_MODEL;
        float2 ra = *(const float2*)(res + idx0);
        float2 rb = *(const float2*)(res + idx1);
        float2 oa, ob;
        oa.x = ra.x + oacc[df][0] * inv0;
        oa.y = ra.y + oacc[df][1] * inv0;
        ob.x = rb.x + oacc[df][2] * inv1;
        ob.y = rb.y + oacc[df][3] * inv1;
        *(float2*)(out + idx0) = oa;
        *(float2*)(out + idx1) = ob;
    }
}

// ---------------------------------------------------------------------------
// mma tf32 GEMM: C[M,N] = A[M,K] @ B[K,N] + bias (+ReLU) (+res).
// Block 64x64, BK=16, 128 threads (4 warps), warp tile 16x64.
// ---------------------------------------------------------------------------
#define AS_STRIDE 20
#define BS_STRIDE 72

template<bool RELU, bool RES>
__global__ void gemm_mma(const float* __restrict__ A,
                         const float* __restrict__ B,
                         const float* __restrict__ bias,
                         const float* __restrict__ res,
                         float* __restrict__ C,
                         int M, int N, int K) {
    __shared__ uint32_t As[64 * AS_STRIDE];   // [m 64][k 16]
    __shared__ uint32_t Bs[16 * BS_STRIDE];   // [k 16][n 64]

    const int n0   = blockIdx.x * 64;
    const int m0   = blockIdx.y * 64;
    const int tid  = threadIdx.x;
    const int lane = tid & 31;
    const int warp = tid >> 5;
    const int g    = lane >> 2;
    const int tig  = lane & 3;

    float acc[8][4];
    #pragma unroll
    for (int i = 0; i < 8; i++)
        #pragma unroll
        for (int j = 0; j < 4; j++) acc[i][j] = 0.0f;

    for (int k0 = 0; k0 < K; k0 += 16) {
        __syncthreads();
        // A tile 64x16 = 256 float4
        #pragma unroll
        for (int i = tid; i < 256; i += 128) {
            int r = i >> 2, cs = (i & 3) << 2;
            float4 v = *(const float4*)(A + (size_t)(m0 + r) * K + k0 + cs);
            uint32_t* d = As + r * AS_STRIDE + cs;
            d[0] = f2tf(v.x); d[1] = f2tf(v.y); d[2] = f2tf(v.z); d[3] = f2tf(v.w);
        }
        // B tile 16x64 = 256 float4
        #pragma unroll
        for (int i = tid; i < 256; i += 128) {
            int r = i >> 4, cs = (i & 15) << 2;
            float4 v = *(const float4*)(B + (size_t)(k0 + r) * N + n0 + cs);
            uint32_t* d = Bs + r * BS_STRIDE + cs;
            d[0] = f2tf(v.x); d[1] = f2tf(v.y); d[2] = f2tf(v.z); d[3] = f2tf(v.w);
        }
        __syncthreads();

        #pragma unroll
        for (int ks = 0; ks < 2; ks++) {
            const uint32_t* aa = As + (warp * 16 + g) * AS_STRIDE + ks * 8 + tig;
            uint32_t a0 = aa[0];
            uint32_t a1 = aa[8 * AS_STRIDE];
            uint32_t a2 = aa[4];
            uint32_t a3 = aa[8 * AS_STRIDE + 4];
            #pragma unroll
            for (int nf = 0; nf < 8; nf++) {
                const uint32_t* bb = Bs + (ks * 8 + tig) * BS_STRIDE + nf * 8 + g;
                mma_tf32(acc[nf], a0, a1, a2, a3, bb[0], bb[4 * BS_STRIDE]);
            }
        }
    }

    const int row0 = m0 + warp * 16 + g;
    #pragma unroll
    for (int nf = 0; nf < 8; nf++) {
        int col = n0 + nf * 8 + 2 * tig;
        float2 bi = *(const float2*)(bias + col);
        size_t idx0 = (size_t)row0 * N + col;
        size_t idx1 = idx0 + (size_t)8 * N;
        float2 va, vb;
        va.x = acc[nf][0] + bi.x; va.y = acc[nf][1] + bi.y;
        vb.x = acc[nf][2] + bi.x; vb.y = acc[nf][3] + bi.y;
        if (RELU) {
            va.x = fmaxf(va.x, 0.0f); va.y = fmaxf(va.y, 0.0f);
            vb.x = fmaxf(vb.x, 0.0f); vb.y = fmaxf(vb.y, 0.0f);
        }
        if (RES) {
            float2 ra = *(const float2*)(res + idx0);
            float2 rb = *(const float2*)(res + idx1);
            va.x += ra.x; va.y += ra.y;
            vb.x += rb.x; vb.y += rb.y;
        }
        *(float2*)(C + idx0) = va;
        *(float2*)(C + idx1) = vb;
    }
}

// ---------------------------------------------------------------------------
extern "C" void kernel_launch(void* const* d_in, const int* in_sizes, int n_in,
                              void* d_out, int out_size) {
    const float* x    = (const float*)d_in[0];
    const float* enc  = (const float*)d_in[1];
    const int*   mask = (const int*)  d_in[2];
    const float* ln1g = (const float*)d_in[3];
    const float* ln1b = (const float*)d_in[4];
    const float* ln2g = (const float*)d_in[5];
    const float* ln2b = (const float*)d_in[6];
    const float* ln3g = (const float*)d_in[7];
    const float* ln3b = (const float*)d_in[8];
    const float* W1   = (const float*)d_in[9];
    const float* b1   = (const float*)d_in[10];
    const float* W2   = (const float*)d_in[11];
    const float* b2   = (const float*)d_in[12];
    float* out = (float*)d_out;

    float *gx, *gxn, *gh;
    cudaGetSymbolAddress((void**)&gx,  g_x);
    cudaGetSymbolAddress((void**)&gxn, g_xn);
    cudaGetSymbolAddress((void**)&gh,  g_h);

    cudaFuncSetAttribute(attn_mma_kernel,
                         cudaFuncAttributeMaxDynamicSharedMemorySize,
                         ATTN_SMEM_BYTES);

    dim3 attn_grid(SEQ / 64, HEADS, BATCH);

    // 1) x1 = LN1(x); x' = x + selfattn(x1, mask)
    ln_kernel<<<NROWS, 128>>>(x, ln1g, ln1b, gxn);
    attn_mma_kernel<<<attn_grid, 128, ATTN_SMEM_BYTES>>>(gxn, gxn, mask, x, gx);

    // 2) x1 = LN2(x'); x'' = x' + crossattn(x1, enc)
    ln_kernel<<<NROWS, 128>>>(gx, ln2g, ln2b, gxn);
    attn_mma_kernel<<<attn_grid, 128, ATTN_SMEM_BYTES>>>(gxn, enc, nullptr, gx, gx);

    // 3) x1 = LN3(x''); out = x'' + relu(x1 W1 + b1) W2 + b2
    ln_kernel<<<NROWS, 128>>>(gx, ln3g, ln3b, gxn);
    gemm_mma<true,  false><<<dim3(D_FF / 64,    NROWS / 64), 128>>>(
        gxn, W1, b1, nullptr, gh, NROWS, D_FF, D_MODEL);
    gemm_mma<false, true ><<<dim3(D_MODEL / 64, NROWS / 64), 128>>>(
        gh, W2, b2, gx, out, NROWS, D_MODEL, D_FF);
}

// round 6
// speedup vs baseline: 2.8401x; 1.0155x over previous
#include <cuda_runtime.h>
#include <math.h>
#include <stdint.h>

#define D_MODEL 512
#define HEADS   8
#define DKH     64
#define SEQ     2048
#define BATCH   4
#define D_FF    1024
#define NROWS   (BATCH*SEQ)   // 8192

// Scratch (static device arrays — no allocation at runtime)
__device__ float g_x [NROWS * D_MODEL];   // running residual stream
__device__ float g_xn[NROWS * D_MODEL];   // layernorm output
__device__ float g_h [NROWS * D_FF];      // FFN hidden

// ---------------------------------------------------------------------------
// tf32 helpers
// ---------------------------------------------------------------------------
__device__ __forceinline__ uint32_t f2tf(float x) {
    uint32_t r;
    asm("cvt.rna.tf32.f32 %0, %1;" : "=r"(r) : "f"(x));
    return r;
}

// D += A(16x8) * B(8x8); A row-major, B col-major.
// a0=A[g][t], a1=A[g+8][t], a2=A[g][t+4], a3=A[g+8][t+4]
// b0=B[t][g], b1=B[t+4][g];  c0=C[g][2t], c1=C[g][2t+1], c2/c3 rows +8
__device__ __forceinline__ void mma_tf32(float c[4],
                                         uint32_t a0, uint32_t a1, uint32_t a2, uint32_t a3,
                                         uint32_t b0, uint32_t b1) {
    asm volatile(
        "mma.sync.aligned.m16n8k8.row.col.f32.tf32.tf32.f32 "
        "{%0,%1,%2,%3}, {%4,%5,%6,%7}, {%8,%9}, {%0,%1,%2,%3};\n"
        : "+f"(c[0]), "+f"(c[1]), "+f"(c[2]), "+f"(c[3])
        : "r"(a0), "r"(a1), "r"(a2), "r"(a3), "r"(b0), "r"(b1));
}

// ---------------------------------------------------------------------------
// LayerNorm: one block per row (512 elems), 128 threads x float4
// ---------------------------------------------------------------------------
__global__ void ln_kernel(const float* __restrict__ x,
                          const float* __restrict__ gamma,
                          const float* __restrict__ beta,
                          float* __restrict__ y) {
    int row = blockIdx.x;
    int t   = threadIdx.x;
    const float4* xr = (const float4*)(x + (size_t)row * D_MODEL);
    float4 v = xr[t];
    float s  = v.x + v.y + v.z + v.w;
    float ss = v.x*v.x + v.y*v.y + v.z*v.z + v.w*v.w;
    #pragma unroll
    for (int o = 16; o > 0; o >>= 1) {
        s  += __shfl_xor_sync(0xffffffffu, s,  o);
        ss += __shfl_xor_sync(0xffffffffu, ss, o);
    }
    __shared__ float as[4], ass[4];
    int w = t >> 5;
    if ((t & 31) == 0) { as[w] = s; ass[w] = ss; }
    __syncthreads();
    s  = as[0]  + as[1]  + as[2]  + as[3];
    ss = ass[0] + ass[1] + ass[2] + ass[3];
    float mu  = s * (1.0f / D_MODEL);
    float var = ss * (1.0f / D_MODEL) - mu * mu;
    float rs  = rsqrtf(var + 1e-5f);
    float4 g4 = ((const float4*)gamma)[t];
    float4 b4 = ((const float4*)beta)[t];
    float4 o4;
    o4.x = (v.x - mu) * rs * g4.x + b4.x;
    o4.y = (v.y - mu) * rs * g4.y + b4.y;
    o4.z = (v.z - mu) * rs * g4.z + b4.z;
    o4.w = (v.w - mu) * rs * g4.w + b4.w;
    ((float4*)(y + (size_t)row * D_MODEL))[t] = o4;
}

// ---------------------------------------------------------------------------
// Flash attention, tf32 mma, BM=128, 4 warps, warp tile 32x64 (2 m-frags).
// Packed smem layouts (uint2 pairs) so every mma fragment is one LDS.64.
//   Qp[r][ks*4+t]   = {Q[r][8ks+t],     Q[r][8ks+t+4]}        stride 36
//   Kp[n][ks*4+t]   = {K[n][8ks+t],     K[n][8ks+t+4]}        stride 36
//   Vp[4ks+t][col]  = {V[8ks+t][col],   V[8ks+t+4][col]}      stride 72
//   Pp[r][4nf+t]    = {P[r][8nf+2t],    P[r][8nf+2t+1]}       stride 38
// ---------------------------------------------------------------------------
#define BM   128
#define QP_S 36
#define KP_S 36
#define VP_S 72
#define PP_S 38
#define ATTN_SMEM_BYTES ((128*QP_S + 64*KP_S + 32*VP_S + 128*PP_S) * 8)

__global__ __launch_bounds__(128, 1)
void attn_mma_kernel(const float* __restrict__ Q,
                     const float* __restrict__ KV,
                     const int*   __restrict__ mask,   // may be null
                     const float* __restrict__ res,
                     float* __restrict__ out) {
    extern __shared__ uint2 sm2[];
    uint2* Qp = sm2;
    uint2* Kp = Qp + 128 * QP_S;
    uint2* Vp = Kp + 64 * KP_S;
    uint2* Pp = Vp + 32 * VP_S;
    uint32_t* PpU = (uint32_t*)Pp;   // u32 stride = 2*PP_S = 76

    const int q0   = blockIdx.x * BM;
    const int h    = blockIdx.y;
    const int b    = blockIdx.z;
    const int tid  = threadIdx.x;
    const int lane = tid & 31;
    const int warp = tid >> 5;
    const int g    = lane >> 2;
    const int tig  = lane & 3;
    const int wrow = warp * 32;

    // ---- Load Q tile [128 x 64] into packed layout ----
    #pragma unroll
    for (int it = 0; it < 8; it++) {
        int i = tid + it * 128;
        int r = i >> 3, ks = i & 7;
        const float* src = Q + ((size_t)(b * SEQ + q0 + r)) * D_MODEL + h * DKH + ks * 8;
        float4 v0 = *(const float4*)src;
        float4 v1 = *(const float4*)(src + 4);
        uint4* d = (uint4*)(Qp + r * QP_S + ks * 4);
        d[0] = make_uint4(f2tf(v0.x), f2tf(v1.x), f2tf(v0.y), f2tf(v1.y));
        d[1] = make_uint4(f2tf(v0.z), f2tf(v1.z), f2tf(v0.w), f2tf(v1.w));
    }

    float oacc[2][8][4];
    #pragma unroll
    for (int mf = 0; mf < 2; mf++)
        #pragma unroll
        for (int i = 0; i < 8; i++)
            #pragma unroll
            for (int j = 0; j < 4; j++) oacc[mf][i][j] = 0.0f;

    float mrow[4] = {-INFINITY, -INFINITY, -INFINITY, -INFINITY};
    float lrow[4] = {0.0f, 0.0f, 0.0f, 0.0f};

    for (int kt = 0; kt < SEQ / 64; kt++) {
        const int k0 = kt * 64;
        __syncthreads();   // protect Kp/Vp reuse (and Qp on first iter)

        // ---- K loader: pairs within row ----
        #pragma unroll
        for (int it = 0; it < 4; it++) {
            int i = tid + it * 128;
            int r = i >> 3, ks = i & 7;
            const float* src = KV + ((size_t)(b * SEQ + k0 + r)) * D_MODEL + h * DKH + ks * 8;
            float4 v0 = *(const float4*)src;
            float4 v1 = *(const float4*)(src + 4);
            uint4* d = (uint4*)(Kp + r * KP_S + ks * 4);
            d[0] = make_uint4(f2tf(v0.x), f2tf(v1.x), f2tf(v0.y), f2tf(v1.y));
            d[1] = make_uint4(f2tf(v0.z), f2tf(v1.z), f2tf(v0.w), f2tf(v1.w));
        }
        // ---- V loader: pairs across rows (r, r+4) ----
        #pragma unroll
        for (int it = 0; it < 4; it++) {
            int i = tid + it * 128;
            int cc = i & 15, tg = (i >> 4) & 3, ks = i >> 6;
            const float* sA = KV + ((size_t)(b * SEQ + k0 + ks * 8 + tg)) * D_MODEL + h * DKH + cc * 4;
            const float* sB = sA + (size_t)4 * D_MODEL;
            float4 a  = *(const float4*)sA;
            float4 bb = *(const float4*)sB;
            uint4* d = (uint4*)(Vp + (ks * 4 + tg) * VP_S + cc * 4);
            d[0] = make_uint4(f2tf(a.x), f2tf(bb.x), f2tf(a.y), f2tf(bb.y));
            d[1] = make_uint4(f2tf(a.z), f2tf(bb.z), f2tf(a.w), f2tf(bb.w));
        }
        __syncthreads();

        // ---- S = Q K^T : warp 32x64, 2 m-frags x 8 n-frags ----
        float sacc[2][8][4];
        #pragma unroll
        for (int mf = 0; mf < 2; mf++)
            #pragma unroll
            for (int i = 0; i < 8; i++)
                #pragma unroll
                for (int j = 0; j < 4; j++) sacc[mf][i][j] = 0.0f;

        #pragma unroll
        for (int ks = 0; ks < 8; ks++) {
            uint2 qa0[2], qa1[2];
            #pragma unroll
            for (int mf = 0; mf < 2; mf++) {
                int rb = wrow + mf * 16;
                qa0[mf] = Qp[(rb + g)     * QP_S + ks * 4 + tig];
                qa1[mf] = Qp[(rb + 8 + g) * QP_S + ks * 4 + tig];
            }
            #pragma unroll
            for (int nf = 0; nf < 8; nf++) {
                uint2 kb = Kp[(nf * 8 + g) * KP_S + ks * 4 + tig];
                mma_tf32(sacc[0][nf], qa0[0].x, qa1[0].x, qa0[0].y, qa1[0].y, kb.x, kb.y);
                mma_tf32(sacc[1][nf], qa0[1].x, qa1[1].x, qa0[1].y, qa1[1].y, kb.x, kb.y);
            }
        }
        #pragma unroll
        for (int mf = 0; mf < 2; mf++)
            #pragma unroll
            for (int i = 0; i < 8; i++)
                #pragma unroll
                for (int j = 0; j < 4; j++) sacc[mf][i][j] *= 0.125f;

        if (mask != nullptr) {
            #pragma unroll
            for (int mf = 0; mf < 2; mf++) {
                int qr = q0 + wrow + mf * 16 + g;
                const int* mr0 = mask + ((size_t)b * SEQ + qr) * SEQ + k0;
                const int* mr1 = mr0 + (size_t)8 * SEQ;
                #pragma unroll
                for (int nf = 0; nf < 8; nf++) {
                    int kc = nf * 8 + 2 * tig;
                    int2 mA = *(const int2*)(mr0 + kc);
                    int2 mB = *(const int2*)(mr1 + kc);
                    if (mA.x == 0) sacc[mf][nf][0] = -1e9f;
                    if (mA.y == 0) sacc[mf][nf][1] = -1e9f;
                    if (mB.x == 0) sacc[mf][nf][2] = -1e9f;
                    if (mB.y == 0) sacc[mf][nf][3] = -1e9f;
                }
            }
        }

        // ---- online softmax: 4 row-streams (j = 2*mf + hi), quad-reduced ----
        float tm[4] = {-INFINITY, -INFINITY, -INFINITY, -INFINITY};
        #pragma unroll
        for (int mf = 0; mf < 2; mf++)
            #pragma unroll
            for (int nf = 0; nf < 8; nf++) {
                tm[2*mf]   = fmaxf(tm[2*mf],   fmaxf(sacc[mf][nf][0], sacc[mf][nf][1]));
                tm[2*mf+1] = fmaxf(tm[2*mf+1], fmaxf(sacc[mf][nf][2], sacc[mf][nf][3]));
            }
        #pragma unroll
        for (int j = 0; j < 4; j++) {
            tm[j] = fmaxf(tm[j], __shfl_xor_sync(0xffffffffu, tm[j], 1));
            tm[j] = fmaxf(tm[j], __shfl_xor_sync(0xffffffffu, tm[j], 2));
        }
        float mn[4], cr[4], se[4];
        #pragma unroll
        for (int j = 0; j < 4; j++) {
            mn[j] = fmaxf(mrow[j], tm[j]);
            cr[j] = __expf(mrow[j] - mn[j]);
            se[j] = 0.0f;
        }
        #pragma unroll
        for (int mf = 0; mf < 2; mf++)
            #pragma unroll
            for (int nf = 0; nf < 8; nf++) {
                float p0 = __expf(sacc[mf][nf][0] - mn[2*mf]);
                float p1 = __expf(sacc[mf][nf][1] - mn[2*mf]);
                float p2 = __expf(sacc[mf][nf][2] - mn[2*mf+1]);
                float p3 = __expf(sacc[mf][nf][3] - mn[2*mf+1]);
                se[2*mf]   += p0 + p1;
                se[2*mf+1] += p2 + p3;
                sacc[mf][nf][0] = p0; sacc[mf][nf][1] = p1;
                sacc[mf][nf][2] = p2; sacc[mf][nf][3] = p3;
            }
        #pragma unroll
        for (int j = 0; j < 4; j++) {
            se[j] += __shfl_xor_sync(0xffffffffu, se[j], 1);
            se[j] += __shfl_xor_sync(0xffffffffu, se[j], 2);
            mrow[j] = mn[j];
            lrow[j] = lrow[j] * cr[j] + se[j];
        }
        #pragma unroll
        for (int mf = 0; mf < 2; mf++)
            #pragma unroll
            for (int df = 0; df < 8; df++) {
                oacc[mf][df][0] *= cr[2*mf];   oacc[mf][df][1] *= cr[2*mf];
                oacc[mf][df][2] *= cr[2*mf+1]; oacc[mf][df][3] *= cr[2*mf+1];
            }

        // ---- store P (tf32, accumulator-pair layout), warp-private rows ----
        #pragma unroll
        for (int mf = 0; mf < 2; mf++) {
            int rp = wrow + mf * 16 + g;
            #pragma unroll
            for (int nf = 0; nf < 8; nf++) {
                Pp[rp       * PP_S + nf * 4 + tig] =
                    make_uint2(f2tf(sacc[mf][nf][0]), f2tf(sacc[mf][nf][1]));
                Pp[(rp + 8) * PP_S + nf * 4 + tig] =
                    make_uint2(f2tf(sacc[mf][nf][2]), f2tf(sacc[mf][nf][3]));
            }
        }
        __syncwarp();

        // ---- O += P V ----
        #pragma unroll
        for (int ks = 0; ks < 8; ks++) {
            uint32_t pa[2][4];
            #pragma unroll
            for (int mf = 0; mf < 2; mf++) {
                int rp = wrow + mf * 16 + g;
                const uint32_t* base = PpU + rp * (2 * PP_S) + ks * 8 + tig;
                pa[mf][0] = base[0];
                pa[mf][1] = base[8 * 2 * PP_S];
                pa[mf][2] = base[4];
                pa[mf][3] = base[8 * 2 * PP_S + 4];
            }
            #pragma unroll
            for (int df = 0; df < 8; df++) {
                uint2 vb = Vp[(ks * 4 + tig) * VP_S + df * 8 + g];
                mma_tf32(oacc[0][df], pa[0][0], pa[0][1], pa[0][2], pa[0][3], vb.x, vb.y);
                mma_tf32(oacc[1][df], pa[1][0], pa[1][1], pa[1][2], pa[1][3], vb.x, vb.y);
            }
        }
    }

    // ---- epilogue: normalize + residual ----
    float inv[4];
    #pragma unroll
    for (int j = 0; j < 4; j++) inv[j] = 1.0f / lrow[j];
    #pragma unroll
    for (int mf = 0; mf < 2; mf++) {
        int r = q0 + wrow + mf * 16 + g;
        #pragma unroll
        for (int df = 0; df < 8; df++) {
            size_t idx0 = ((size_t)(b * SEQ + r)) * D_MODEL + h * DKH + df * 8 + 2 * tig;
            size_t idx1 = idx0 + (size_t)8 * D_MODEL;
            float2 ra = *(const float2*)(res + idx0);
            float2 rb = *(const float2*)(res + idx1);
            float2 oa, ob;
            oa.x = ra.x + oacc[mf][df][0] * inv[2*mf];
            oa.y = ra.y + oacc[mf][df][1] * inv[2*mf];
            ob.x = rb.x + oacc[mf][df][2] * inv[2*mf+1];
            ob.y = rb.y + oacc[mf][df][3] * inv[2*mf+1];
            *(float2*)(out + idx0) = oa;
            *(float2*)(out + idx1) = ob;
        }
    }
}

// ---------------------------------------------------------------------------
// tf32 mma GEMM: C[M,N] = A[M,K] @ B[K,N] + bias (+ReLU) (+res).
// Block 128x64, BK=32, 128 threads (4 warps), warp tile 32x64, packed layouts.
// ---------------------------------------------------------------------------
#define GA_S 20   // uint2 stride per A row (16 pad 20)
#define GB_S 72   // uint2 stride per B (ks,t) row-pair

template<bool RELU, bool RES>
__global__ __launch_bounds__(128, 1)
void gemm_mma(const float* __restrict__ A,
              const float* __restrict__ B,
              const float* __restrict__ bias,
              const float* __restrict__ res,
              float* __restrict__ C,
              int M, int N, int K) {
    __shared__ uint2 Ap[128 * GA_S];
    __shared__ uint2 Bp[16 * GB_S];

    const int n0   = blockIdx.x * 64;
    const int m0   = blockIdx.y * 128;
    const int tid  = threadIdx.x;
    const int lane = tid & 31;
    const int warp = tid >> 5;
    const int g    = lane >> 2;
    const int tig  = lane & 3;
    const int wrow = warp * 32;

    float acc[2][8][4];
    #pragma unroll
    for (int mf = 0; mf < 2; mf++)
        #pragma unroll
        for (int i = 0; i < 8; i++)
            #pragma unroll
            for (int j = 0; j < 4; j++) acc[mf][i][j] = 0.0f;

    for (int k0 = 0; k0 < K; k0 += 32) {
        __syncthreads();
        // A loader: 128 rows x 4 ks-chunks
        #pragma unroll
        for (int it = 0; it < 4; it++) {
            int i = tid + it * 128;
            int r = i >> 2, ks = i & 3;
            const float* src = A + (size_t)(m0 + r) * K + k0 + ks * 8;
            float4 v0 = *(const float4*)src;
            float4 v1 = *(const float4*)(src + 4);
            uint4* d = (uint4*)(Ap + r * GA_S + ks * 4);
            d[0] = make_uint4(f2tf(v0.x), f2tf(v1.x), f2tf(v0.y), f2tf(v1.y));
            d[1] = make_uint4(f2tf(v0.z), f2tf(v1.z), f2tf(v0.w), f2tf(v1.w));
        }
        // B loader: pairs across rows (k, k+4)
        #pragma unroll
        for (int it = 0; it < 2; it++) {
            int i = tid + it * 128;
            int cc = i & 15, tg = (i >> 4) & 3, ks = i >> 6;
            const float* sA = B + (size_t)(k0 + ks * 8 + tg) * N + n0 + cc * 4;
            const float* sB = sA + (size_t)4 * N;
            float4 a  = *(const float4*)sA;
            float4 bb = *(const float4*)sB;
            uint4* d = (uint4*)(Bp + (ks * 4 + tg) * GB_S + cc * 4);
            d[0] = make_uint4(f2tf(a.x), f2tf(bb.x), f2tf(a.y), f2tf(bb.y));
            d[1] = make_uint4(f2tf(a.z), f2tf(bb.z), f2tf(a.w), f2tf(bb.w));
        }
        __syncthreads();

        #pragma unroll
        for (int ks = 0; ks < 4; ks++) {
            uint2 aa0[2], aa1[2];
            #pragma unroll
            for (int mf = 0; mf < 2; mf++) {
                int rb = wrow + mf * 16;
                aa0[mf] = Ap[(rb + g)     * GA_S + ks * 4 + tig];
                aa1[mf] = Ap[(rb + 8 + g) * GA_S + ks * 4 + tig];
            }
            #pragma unroll
            for (int nf = 0; nf < 8; nf++) {
                uint2 bb = Bp[(ks * 4 + tig) * GB_S + nf * 8 + g];
                mma_tf32(acc[0][nf], aa0[0].x, aa1[0].x, aa0[0].y, aa1[0].y, bb.x, bb.y);
                mma_tf32(acc[1][nf], aa0[1].x, aa1[1].x, aa0[1].y, aa1[1].y, bb.x, bb.y);
            }
        }
    }

    #pragma unroll
    for (int mf = 0; mf < 2; mf++) {
        int row0 = m0 + wrow + mf * 16 + g;
        #pragma unroll
        for (int nf = 0; nf < 8; nf++) {
            int col = n0 + nf * 8 + 2 * tig;
            float2 bi = *(const float2*)(bias + col);
            size_t idx0 = (size_t)row0 * N + col;
            size_t idx1 = idx0 + (size_t)8 * N;
            float2 va, vb;
            va.x = acc[mf][nf][0] + bi.x; va.y = acc[mf][nf][1] + bi.y;
            vb.x = acc[mf][nf][2] + bi.x; vb.y = acc[mf][nf][3] + bi.y;
            if (RELU) {
                va.x = fmaxf(va.x, 0.0f); va.y = fmaxf(va.y, 0.0f);
                vb.x = fmaxf(vb.x, 0.0f); vb.y = fmaxf(vb.y, 0.0f);
            }
            if (RES) {
                float2 ra = *(const float2*)(res + idx0);
                float2 rb = *(const float2*)(res + idx1);
                va.x += ra.x; va.y += ra.y;
                vb.x += rb.x; vb.y += rb.y;
            }
            *(float2*)(C + idx0) = va;
            *(float2*)(C + idx1) = vb;
        }
    }
}

// ---------------------------------------------------------------------------
extern "C" void kernel_launch(void* const* d_in, const int* in_sizes, int n_in,
                              void* d_out, int out_size) {
    const float* x    = (const float*)d_in[0];
    const float* enc  = (const float*)d_in[1];
    const int*   mask = (const int*)  d_in[2];
    const float* ln1g = (const float*)d_in[3];
    const float* ln1b = (const float*)d_in[4];
    const float* ln2g = (const float*)d_in[5];
    const float* ln2b = (const float*)d_in[6];
    const float* ln3g = (const float*)d_in[7];
    const float* ln3b = (const float*)d_in[8];
    const float* W1   = (const float*)d_in[9];
    const float* b1   = (const float*)d_in[10];
    const float* W2   = (const float*)d_in[11];
    const float* b2   = (const float*)d_in[12];
    float* out = (float*)d_out;

    float *gx, *gxn, *gh;
    cudaGetSymbolAddress((void**)&gx,  g_x);
    cudaGetSymbolAddress((void**)&gxn, g_xn);
    cudaGetSymbolAddress((void**)&gh,  g_h);

    cudaFuncSetAttribute(attn_mma_kernel,
                         cudaFuncAttributeMaxDynamicSharedMemorySize,
                         ATTN_SMEM_BYTES);

    dim3 attn_grid(SEQ / BM, HEADS, BATCH);

    // 1) x1 = LN1(x); x' = x + selfattn(x1, mask)
    ln_kernel<<<NROWS, 128>>>(x, ln1g, ln1b, gxn);
    attn_mma_kernel<<<attn_grid, 128, ATTN_SMEM_BYTES>>>(gxn, gxn, mask, x, gx);

    // 2) x1 = LN2(x'); x'' = x' + crossattn(x1, enc)
    ln_kernel<<<NROWS, 128>>>(gx, ln2g, ln2b, gxn);
    attn_mma_kernel<<<attn_grid, 128, ATTN_SMEM_BYTES>>>(gxn, enc, nullptr, gx, gx);

    // 3) x1 = LN3(x''); out = x'' + relu(x1 W1 + b1) W2 + b2
    ln_kernel<<<NROWS, 128>>>(gx, ln3g, ln3b, gxn);
    gemm_mma<true,  false><<<dim3(D_FF / 64,    NROWS / 128), 128>>>(
        gxn, W1, b1, nullptr, gh, NROWS, D_FF, D_MODEL);
    gemm_mma<false, true ><<<dim3(D_MODEL / 64, NROWS / 128), 128>>>(
        gh, W2, b2, gx, out, NROWS, D_MODEL, D_FF);
}